// round 3
// baseline (speedup 1.0000x reference)
#include <cuda_runtime.h>
#include <math.h>

// Problem constants
#define Bb 32
#define Tt 128
#define Hh 1024
#define Ll 2
#define Vv 32000
#define H3 3072          // 3*H
#define MROWS (Tt*Bb)    // 4096
#define BOS 1
#define KSPLIT 8

// ---------------- scratch (static device globals; no runtime allocation) ----
__device__ float g_gi[MROWS * H3];        // gi for the current layer [t*B+b][3H]  (50.3 MB)
__device__ float g_h0[MROWS * Hh];        // layer-0 outputs [t*B+b][H]            (16.8 MB)
__device__ float g_hs[MROWS * Hh];        // layer-1 outputs [b*T+t][H]            (16.8 MB)
__device__ float g_state[Ll * Bb * Hh];   // running hidden state per layer
__device__ float g_gh[KSPLIT * Bb * H3];  // K-split partial gh per step           (3.1 MB)
__device__ int   g_ids[MROWS];            // teacher-forced input ids, [t*B+b]
__device__ float g_lse[MROWS];            // per-row logsumexp

// ---------------- simple float copy (graph-safe, replaces memcpyAsync) ------
__global__ void copy_kernel(const float* __restrict__ src, float* __restrict__ dst, int n) {
    int i = blockIdx.x * blockDim.x + threadIdx.x;
    if (i < n) dst[i] = src[i];
}

// ---------------- ids: [BOS, target[:, :-1]] --------------------------------
__global__ void ids_kernel(const int* __restrict__ target) {
    int i = blockIdx.x * blockDim.x + threadIdx.x;   // i = t*B + b
    if (i >= MROWS) return;
    int t = i / Bb, b = i % Bb;
    g_ids[i] = (t == 0) ? BOS : target[b * Tt + (t - 1)];
}

// ---------------- 128x128 fp32 SGEMM:  C[m][n] = sum_k A[m][k]*W[n][k] + bias[n]
// A rows either direct (A + row*K) or gathered from embedding via g_ids.
template<int GATHER>
__global__ void __launch_bounds__(256, 2) sgemm_kernel(
    const float* __restrict__ A, const float* __restrict__ Wt,
    const float* __restrict__ bias, float* __restrict__ C,
    int N, int Kdim, const float* __restrict__ emb)
{
    __shared__ float As[8][128];
    __shared__ float Bs[8][128];
    int tid = threadIdx.x;
    int m0 = blockIdx.y * 128;
    int n0 = blockIdx.x * 128;
    int tx = tid & 15, ty = tid >> 4;
    float acc[8][8];
    #pragma unroll
    for (int i = 0; i < 8; i++)
        #pragma unroll
        for (int j = 0; j < 8; j++) acc[i][j] = 0.f;

    int lr = tid >> 1;            // 0..127: row within tile
    int lk = (tid & 1) * 4;       // 0 or 4: k quad
    const float* arow;
    if (GATHER) arow = emb + (size_t)g_ids[m0 + lr] * Kdim;
    else        arow = A + (size_t)(m0 + lr) * Kdim;
    const float* brow = Wt + (size_t)(n0 + lr) * Kdim;

    for (int k0 = 0; k0 < Kdim; k0 += 8) {
        float4 av = *(const float4*)(arow + k0 + lk);
        float4 bv = *(const float4*)(brow + k0 + lk);
        As[lk + 0][lr] = av.x; As[lk + 1][lr] = av.y;
        As[lk + 2][lr] = av.z; As[lk + 3][lr] = av.w;
        Bs[lk + 0][lr] = bv.x; Bs[lk + 1][lr] = bv.y;
        Bs[lk + 2][lr] = bv.z; Bs[lk + 3][lr] = bv.w;
        __syncthreads();
        #pragma unroll
        for (int kk = 0; kk < 8; kk++) {
            float a[8], b[8];
            #pragma unroll
            for (int i = 0; i < 8; i++) a[i] = As[kk][ty + 16 * i];
            #pragma unroll
            for (int j = 0; j < 8; j++) b[j] = Bs[kk][tx + 16 * j];
            #pragma unroll
            for (int i = 0; i < 8; i++)
                #pragma unroll
                for (int j = 0; j < 8; j++)
                    acc[i][j] += a[i] * b[j];
        }
        __syncthreads();
    }
    #pragma unroll
    for (int i = 0; i < 8; i++) {
        int m = m0 + ty + 16 * i;
        #pragma unroll
        for (int j = 0; j < 8; j++) {
            int n = n0 + tx + 16 * j;
            C[(size_t)m * N + n] = acc[i][j] + (bias ? bias[n] : 0.f);
        }
    }
}

// ---------------- per-step recurrence GEMM (K-split): gh partials ------------
// block (nTile, ks): computes partial over K chunk ks for 64 output cols.
__global__ void __launch_bounds__(256) step_gemm(const float* __restrict__ h,
                                                 const float* __restrict__ whh)
{
    __shared__ float hS[16][32];
    __shared__ float wS[16][64];
    int tid = threadIdx.x;
    int n0 = blockIdx.x * 64;
    int ks = blockIdx.y;
    int r  = tid & 31;
    int cg = tid >> 5;
    float acc[8];
    #pragma unroll
    for (int j = 0; j < 8; j++) acc[j] = 0.f;

    int kbase0 = ks * (Hh / KSPLIT);   // 128-wide K chunk
    for (int s = 0; s < Hh / KSPLIT; s += 16) {
        int kb = kbase0 + s;
        if (tid < 128) {
            int rr = tid & 31;
            int kq = (tid >> 5) * 4;
            float4 v = *(const float4*)(h + (size_t)rr * Hh + kb + kq);
            hS[kq + 0][rr] = v.x; hS[kq + 1][rr] = v.y;
            hS[kq + 2][rr] = v.z; hS[kq + 3][rr] = v.w;
        }
        {
            int cc = tid & 63;
            int kq = (tid >> 6) * 4;
            float4 v = *(const float4*)(whh + (size_t)(n0 + cc) * Hh + kb + kq);
            wS[kq + 0][cc] = v.x; wS[kq + 1][cc] = v.y;
            wS[kq + 2][cc] = v.z; wS[kq + 3][cc] = v.w;
        }
        __syncthreads();
        #pragma unroll
        for (int kk = 0; kk < 16; kk++) {
            float a = hS[kk][r];
            #pragma unroll
            for (int j = 0; j < 8; j++)
                acc[j] += a * wS[kk][cg * 8 + j];
        }
        __syncthreads();
    }
    float* dst = g_gh + (size_t)(ks * Bb + r) * H3 + n0 + cg * 8;
    #pragma unroll
    for (int j = 0; j < 8; j++) dst[j] = acc[j];
}

// ---------------- per-step gate math; writes new h to state + history --------
__global__ void gates_kernel(const float* __restrict__ gi_t,
                             const float* __restrict__ bhh,
                             float* __restrict__ hstate,
                             float* __restrict__ houtBase, int bStride)
{
    int i = blockIdx.x * 256 + threadIdx.x;   // < B*H
    int b = i / Hh, j = i % Hh;
    float ghr = 0.f, ghz = 0.f, ghn = 0.f;
    #pragma unroll
    for (int s = 0; s < KSPLIT; s++) {
        const float* p = g_gh + (size_t)(s * Bb + b) * H3;
        ghr += p[j]; ghz += p[Hh + j]; ghn += p[2 * Hh + j];
    }
    ghr += bhh[j]; ghz += bhh[Hh + j]; ghn += bhh[2 * Hh + j];
    const float* gi = gi_t + (size_t)b * H3;
    float r = 1.f / (1.f + expf(-(gi[j] + ghr)));
    float z = 1.f / (1.f + expf(-(gi[Hh + j] + ghz)));
    float n = tanhf(gi[2 * Hh + j] + r * ghn);
    float hprev = hstate[(size_t)b * Hh + j];
    float hnew = (1.f - z) * n + z * hprev;
    hstate[(size_t)b * Hh + j] = hnew;
    houtBase[(size_t)b * bStride + j] = hnew;
}

// ---------------- per-row logsumexp over V ----------------------------------
__global__ void lse_kernel(const float* __restrict__ logits) {
    int row = blockIdx.x;
    const float* p = logits + (size_t)row * Vv;
    __shared__ float warpred[8];
    int lane = threadIdx.x & 31, wid = threadIdx.x >> 5;

    float mx = -1e30f;
    for (int i = threadIdx.x; i < Vv; i += 256) mx = fmaxf(mx, p[i]);
    #pragma unroll
    for (int s = 16; s > 0; s >>= 1)
        mx = fmaxf(mx, __shfl_xor_sync(0xffffffffu, mx, s));
    if (lane == 0) warpred[wid] = mx;
    __syncthreads();
    mx = warpred[lane & 7];
    #pragma unroll
    for (int s = 4; s > 0; s >>= 1)
        mx = fmaxf(mx, __shfl_xor_sync(0xffffffffu, mx, s));
    mx = __shfl_sync(0xffffffffu, mx, 0);

    float sum = 0.f;
    for (int i = threadIdx.x; i < Vv; i += 256) sum += expf(p[i] - mx);
    #pragma unroll
    for (int s = 16; s > 0; s >>= 1)
        sum += __shfl_xor_sync(0xffffffffu, sum, s);
    __syncthreads();
    if (lane == 0) warpred[wid] = sum;
    __syncthreads();
    if (threadIdx.x == 0) {
        float tot = 0.f;
        #pragma unroll
        for (int w = 0; w < 8; w++) tot += warpred[w];
        g_lse[row] = mx + logf(tot);
    }
}

__global__ void sub_kernel(float* __restrict__ out) {
    int row = blockIdx.y;
    int c = blockIdx.x * 256 + threadIdx.x;
    out[(size_t)row * Vv + c] -= g_lse[row];
}

// ---------------- host driver ------------------------------------------------
extern "C" void kernel_launch(void* const* d_in, const int* in_sizes, int n_in,
                              void* d_out, int out_size) {
    const float* enc_h  = (const float*)d_in[1];
    const int*   target = (const int*)  d_in[2];
    const float* emb    = (const float*)d_in[3];
    const float* w_ih   = (const float*)d_in[4];
    const float* w_hh   = (const float*)d_in[5];
    const float* b_ih   = (const float*)d_in[6];
    const float* b_hh   = (const float*)d_in[7];
    const float* w_out  = (const float*)d_in[8];
    const float* b_out  = (const float*)d_in[9];
    float* out = (float*)d_out;

    float *p_gi, *p_h0, *p_hs, *p_state;
    cudaGetSymbolAddress((void**)&p_gi,    g_gi);
    cudaGetSymbolAddress((void**)&p_h0,    g_h0);
    cudaGetSymbolAddress((void**)&p_hs,    g_hs);
    cudaGetSymbolAddress((void**)&p_state, g_state);

    // h state <- encoder_hidden (kernel copy; graph-safe)
    copy_kernel<<<(Ll * Bb * Hh + 255) / 256, 256, 0, 0>>>(
        enc_h, p_state, Ll * Bb * Hh);

    // teacher-forced ids
    ids_kernel<<<(MROWS + 255) / 256, 256, 0, 0>>>(target);

    // ---- layer 0: gi0 = embed(ids) @ w_ih0^T + b_ih0 (big batched GEMM) ----
    sgemm_kernel<1><<<dim3(H3 / 128, MROWS / 128), 256, 0, 0>>>(
        nullptr, w_ih, b_ih, p_gi, H3, Hh, emb);

    // layer-0 recurrence
    for (int t = 0; t < Tt; t++) {
        step_gemm<<<dim3(H3 / 64, KSPLIT), 256, 0, 0>>>(p_state, w_hh);
        gates_kernel<<<(Bb * Hh) / 256, 256, 0, 0>>>(
            p_gi + (size_t)t * Bb * H3, b_hh, p_state,
            p_h0 + (size_t)t * Bb * Hh, Hh);
    }

    // ---- layer 1: gi1 = h0 @ w_ih1^T + b_ih1 -------------------------------
    sgemm_kernel<0><<<dim3(H3 / 128, MROWS / 128), 256, 0, 0>>>(
        p_h0, w_ih + (size_t)H3 * Hh, b_ih + H3, p_gi, H3, Hh, nullptr);

    // layer-1 recurrence (outputs in [b][t][h] order for the logits GEMM)
    for (int t = 0; t < Tt; t++) {
        step_gemm<<<dim3(H3 / 64, KSPLIT), 256, 0, 0>>>(
            p_state + Bb * Hh, w_hh + (size_t)H3 * Hh);
        gates_kernel<<<(Bb * Hh) / 256, 256, 0, 0>>>(
            p_gi + (size_t)t * Bb * H3, b_hh + H3, p_state + Bb * Hh,
            p_hs + (size_t)t * Hh, Tt * Hh);
    }

    // ---- logits = hs @ w_out^T + b_out  -> d_out[b][t][v] ------------------
    sgemm_kernel<0><<<dim3(Vv / 128, MROWS / 128), 256, 0, 0>>>(
        p_hs, w_out, b_out, out, Vv, Hh, nullptr);

    // ---- log_softmax -------------------------------------------------------
    lse_kernel<<<MROWS, 256, 0, 0>>>(out);
    sub_kernel<<<dim3(Vv / 256, MROWS), 256, 0, 0>>>(out);

    // ---- h_final (kernel copy; graph-safe) ---------------------------------
    copy_kernel<<<(Ll * Bb * Hh + 255) / 256, 256, 0, 0>>>(
        p_state, out + (size_t)MROWS * Vv, Ll * Bb * Hh);
}